// round 16
// baseline (speedup 1.0000x reference)
#include <cuda_runtime.h>
#include <cuda_fp16.h>
#include <cstdint>

#define N_NODES 50000
#define N_EDGES 1600000
#define N_GRAPHS 2048
#define D 133
#define DP 136           // fp32 padded row (floats)
#define DPH 144          // fp16 padded row (halves) = 288B (9 sectors)
#define WKS 152          // W smem k-stride in halves (bank-conflict-free)
#define WN  144          // W smem n-rows (padded for uniform 18 tiles)
#define EPSV 1e-5f
#define SCAN_B 1024
#define SCAN_NB ((N_NODES + SCAN_B - 1) / SCAN_B)   // 49

// -------- scratch (static device globals; no runtime allocation) --------
__device__ __align__(16) __half g_A16[(size_t)N_NODES * DPH];  // gemm out (messages)
__device__ __align__(16) __half g_X16[(size_t)N_NODES * DPH];  // gemm in
__device__ __align__(16) float  g_P[(size_t)N_GRAPHS * DP];    // pool accumulator
__device__ __align__(16) __half g_W2th[WN * WKS];              // W2 fp16, [n][k] transposed
__device__ int   g_cnt[N_NODES];
__device__ int   g_off[N_NODES + 1];
__device__ int   g_cursor[N_NODES];
__device__ int   g_csr[N_EDGES];
__device__ int   g_bsum[SCAN_NB];
__device__ int   g_cntg[N_GRAPHS];
__device__ float g_post1[3 * DP];    // bias | s | t   (zero-padded)
__device__ float g_post2[3 * DP];

// ------------------------------------------------------------------
__global__ void zero_fused_kernel() {
    int i = blockIdx.x * blockDim.x + threadIdx.x;
    if (i < N_GRAPHS * DP) g_P[i] = 0.0f;
    if (i < N_NODES)       g_cnt[i] = 0;
}

__global__ void count_deg_kernel(const int* __restrict__ ei) {
    int e = blockIdx.x * blockDim.x + threadIdx.x;
    if (e < N_EDGES) atomicAdd(&g_cnt[__ldg(&ei[N_EDGES + e])], 1);
}

__device__ __forceinline__ uint32_t pack2h(float x, float y) {
    __half2 h = __floats2half2_rn(x, y);
    return *(uint32_t*)&h;
}

// X (fp32 [N,133]) -> g_X16 (fp16 [N,144], pads 0). Independent of everything.
__global__ void prep_x_kernel(const float* __restrict__ X) {
    int idx = blockIdx.x * blockDim.x + threadIdx.x;
    if (idx >= N_NODES * 36) return;
    int row = idx / 36;
    int q   = idx - row * 36;
    int c   = 4 * q;
    const float* Xr = X + (size_t)row * D;
    float f0 = (c     < D) ? __ldg(Xr + c)     : 0.0f;
    float f1 = (c + 1 < D) ? __ldg(Xr + c + 1) : 0.0f;
    float f2 = (c + 2 < D) ? __ldg(Xr + c + 2) : 0.0f;
    float f3 = (c + 3 < D) ? __ldg(Xr + c + 3) : 0.0f;
    ((uint2*)(g_X16 + (size_t)row * DPH))[q] = make_uint2(pack2h(f0, f1), pack2h(f2, f3));
}

// ---- 3-kernel exclusive scan of g_cnt -> g_off ----
__global__ void scan1_kernel() {
    __shared__ int sh[SCAN_B];
    int t = threadIdx.x;
    int i = blockIdx.x * SCAN_B + t;
    int v = (i < N_NODES) ? g_cnt[i] : 0;
    sh[t] = v;
    __syncthreads();
#pragma unroll
    for (int d = 1; d < SCAN_B; d <<= 1) {
        int x = (t >= d) ? sh[t - d] : 0;
        __syncthreads();
        sh[t] += x;
        __syncthreads();
    }
    if (i < N_NODES) g_off[i] = sh[t] - v;
    if (t == SCAN_B - 1) g_bsum[blockIdx.x] = sh[t];
}

__global__ void scan2_kernel() {
    if (threadIdx.x == 0) {
        int acc = 0;
        for (int b = 0; b < SCAN_NB; b++) {
            int v = g_bsum[b];
            g_bsum[b] = acc;
            acc += v;
        }
    }
}

__global__ void scan3_kernel() {
    int i = blockIdx.x * blockDim.x + threadIdx.x;
    if (i < N_NODES) {
        int o = g_off[i] + g_bsum[i / SCAN_B];
        g_off[i] = o;
        g_cursor[i] = o;
    }
    if (i == 0) g_off[N_NODES] = N_EDGES;
}

__global__ void fill_csr_kernel(const int* __restrict__ ei) {
    int e = blockIdx.x * blockDim.x + threadIdx.x;
    if (e < N_EDGES) {
        int r = __ldg(&ei[e]);
        int c = __ldg(&ei[N_EDGES + e]);
        int pos = atomicAdd(&g_cursor[c], 1);
        g_csr[pos] = r;
    }
}

// ---- per-layer fused BN constants: bias | s | t, zero-padded to DP ----
__global__ void prep_post_kernel(const float* __restrict__ bias, const float* __restrict__ gam,
                                 const float* __restrict__ beta, const float* __restrict__ rm,
                                 const float* __restrict__ rv, float* __restrict__ dst) {
    int c = threadIdx.x;
    if (c >= DP) return;
    float bb = 0.0f, ss = 0.0f, tt = 0.0f;
    if (c < D) {
        bb = bias[c];
        float sc = gam[c] * rsqrtf(rv[c] + EPSV);
        ss = sc;
        tt = beta[c] - rm[c] * sc;
    }
    dst[c] = bb; dst[DP + c] = ss; dst[2 * DP + c] = tt;
}

// W2 -> fp16, transposed [n][k], n padded to WN rows, zero-padded
__global__ void w_cvt_h_kernel(const float* __restrict__ W, __half* __restrict__ Wt) {
    int i = blockIdx.x * blockDim.x + threadIdx.x;
    if (i >= WN * WKS) return;
    int n = i / WKS, k = i - n * WKS;
    float v = (k < D && n < D) ? __ldg(&W[k * D + n]) : 0.0f;
    Wt[i] = __float2half(v);
}

__device__ __forceinline__ void mma_f16(float* d,
                                        uint32_t a0, uint32_t a1, uint32_t a2, uint32_t a3,
                                        uint32_t b0, uint32_t b1) {
    asm volatile("mma.sync.aligned.m16n8k16.row.col.f32.f16.f16.f32 "
                 "{%0,%1,%2,%3}, {%4,%5,%6,%7}, {%8,%9}, {%0,%1,%2,%3};"
                 : "+f"(d[0]), "+f"(d[1]), "+f"(d[2]), "+f"(d[3])
                 : "r"(a0), "r"(a1), "r"(a2), "r"(a3), "r"(b0), "r"(b1));
}

// Tensor-core GEMM (fp16 m16n8k16): g_A16[row] = fp16( rsqrt(cnt+1) * (Xh @ W) ).
// W in smem [WN=144 n][WKS k] -> UNIFORM 9 n-tiles per warp (18 tiles, 144 cols);
// tiles >=17 hit zero W rows and write zero pads. No runtime tile predication.
template <bool CVT>
__global__ __launch_bounds__(256, 4)
void gemm_tc_kernel(const __half* __restrict__ Xh,
                    const float* __restrict__ Wf, const __half* __restrict__ Wth) {
    extern __shared__ __half wsh[];          // [WN][WKS] fp16

    int tid  = threadIdx.x;
    int w    = tid >> 5;
    int lane = tid & 31;

    if (CVT) {
        // one pass over all WN*WKS/2 words: convert or zero
        const int WPR = WKS / 2;             // 76 words per row
        for (int idx = tid; idx < WN * WPR; idx += 256) {
            int n  = idx / WPR;
            int wi = idx - n * WPR;
            int k0 = 2 * wi;
            float f0 = (k0 < D     && n < D) ? __ldg(&Wf[k0 * D + n])       : 0.0f;
            float f1 = (k0 + 1 < D && n < D) ? __ldg(&Wf[(k0 + 1) * D + n]) : 0.0f;
            *(uint32_t*)&wsh[n * WKS + k0] = pack2h(f0, f1);
        }
    } else {
        const uint4* src = (const uint4*)Wth;
        uint4* dst = (uint4*)wsh;
#pragma unroll 4
        for (int i = tid; i < (WN * WKS) / 8; i += 256) dst[i] = __ldg(&src[i]);
    }
    __syncthreads();

    const int r0 = lane >> 2;        // A row group / B n
    const int kc = lane & 3;         // A k quad / B k
    const int colhalf = w & 1;
    const int ntBase = colhalf * 9;  // tiles 0..8 or 9..17

    int rowbase = blockIdx.x * 64 + (w >> 1) * 16;
    int row0 = rowbase + r0;
    int row1 = row0 + 8;
    bool v0 = row0 < N_NODES;
    bool v1 = row1 < N_NODES;
    const uint32_t* x0p = (const uint32_t*)(Xh + (size_t)(v0 ? row0 : 0) * DPH);
    const uint32_t* x1p = (const uint32_t*)(Xh + (size_t)(v1 ? row1 : 0) * DPH);

    const uint32_t* wb = (const uint32_t*)&wsh[(ntBase * 8 + r0) * WKS + 2 * kc];

    float acc[9][4];
#pragma unroll
    for (int j = 0; j < 9; j++)
#pragma unroll
        for (int q = 0; q < 4; q++) acc[j][q] = 0.0f;

    uint32_t a0 = __ldg(x0p + kc);
    uint32_t a1 = __ldg(x1p + kc);
    uint32_t a2 = __ldg(x0p + kc + 4);
    uint32_t a3 = __ldg(x1p + kc + 4);

#pragma unroll
    for (int ks = 0; ks < 9; ks++) {
        uint32_t na0 = 0, na1 = 0, na2 = 0, na3 = 0;
        if (ks < 8) {
            int wi = (ks + 1) * 8 + kc;
            na0 = __ldg(x0p + wi);
            na1 = __ldg(x1p + wi);
            na2 = __ldg(x0p + wi + 4);
            na3 = __ldg(x1p + wi + 4);
        }
#pragma unroll
        for (int j = 0; j < 9; j++)
            mma_f16(acc[j], a0, a1, a2, a3,
                    wb[j * (4 * WKS) + ks * 8], wb[j * (4 * WKS) + ks * 8 + 4]);
        a0 = na0; a1 = na1; a2 = na2; a3 = na3;
    }

    // epilogue: inline dinv = rsqrt(cnt+1); fp16 half2 stores (cols up to 143)
    float dv0 = v0 ? rsqrtf((float)(__ldg(&g_cnt[row0]) + 1)) : 0.0f;
    float dv1 = v1 ? rsqrtf((float)(__ldg(&g_cnt[row1]) + 1)) : 0.0f;
    int cb = 2 * kc;
#pragma unroll
    for (int j = 0; j < 9; j++) {
        int c = (ntBase + j) * 8 + cb;
        if (v0)
            *(__half2*)(g_A16 + (size_t)row0 * DPH + c) =
                __floats2half2_rn(dv0 * acc[j][0], dv0 * acc[j][1]);
        if (v1)
            *(__half2*)(g_A16 + (size_t)row1 * DPH + c) =
                __floats2half2_rn(dv1 * acc[j][2], dv1 * acc[j][3]);
    }
}

// ------------------------------------------------------------------
// Warp-per-node CSR gather, full-warp lanes: lane l accumulates cols 4l..4l+3
// (uint2 = 2 half2); lanes 0-1 also handle tail cols 128..135. fp32 accum.
// POOL=0: write fp16 row (DPH, pads zeroed) to g_X16.  POOL=1: red.v4 into g_P.
template <int POOL>
__global__ __launch_bounds__(256)
void gather_post_kernel(const __half* __restrict__ A,
                        const float* __restrict__ post,
                        const int* __restrict__ batch) {
    int gw = (blockIdx.x * blockDim.x + threadIdx.x) >> 5;
    if (gw >= N_NODES) return;
    int lane = threadIdx.x & 31;
    int n = gw;

    int lo = __ldg(&g_off[n]);
    int hi = __ldg(&g_off[n + 1]);
    bool tl = lane < 2;

    float a0 = 0.f, a1 = 0.f, a2 = 0.f, a3 = 0.f;
    float t0 = 0.f, t1 = 0.f, t2 = 0.f, t3 = 0.f;

#define ACCUM(SJ) do {                                                        \
        const char* R = (const char*)(A + (size_t)(SJ) * DPH);                \
        uint2 m = __ldg((const uint2*)R + lane);                              \
        float2 f0 = __half22float2(*(const __half2*)&m.x);                    \
        float2 f1 = __half22float2(*(const __half2*)&m.y);                    \
        a0 += f0.x; a1 += f0.y; a2 += f1.x; a3 += f1.y;                       \
        if (tl) {                                                             \
            uint2 mt = __ldg((const uint2*)(R + 256) + lane);                 \
            float2 g0 = __half22float2(*(const __half2*)&mt.x);               \
            float2 g1 = __half22float2(*(const __half2*)&mt.y);               \
            t0 += g0.x; t1 += g0.y; t2 += g1.x; t3 += g1.y;                   \
        }                                                                     \
    } while (0)

    ACCUM(n);   // self-loop term

    int e = lo;
    for (; e + 32 <= hi; e += 32) {
        int src = __ldg(&g_csr[e + lane]);
#pragma unroll 4
        for (int j = 0; j < 32; j++) {
            int sj = __shfl_sync(0xffffffffu, src, j);
            ACCUM(sj);
        }
    }
    for (; e < hi; e++) {
        int sj = __ldg(&g_csr[e]);
        ACCUM(sj);
    }
#undef ACCUM

    float dv = rsqrtf((float)(__ldg(&g_cnt[n]) + 1));
    const float* bb = post;
    const float* ss = post + DP;
    const float* tt = post + 2 * DP;

    int c0 = 4 * lane;
    float4 o;
    o.x = fmaf(fmaxf(fmaf(dv, a0, __ldg(&bb[c0 + 0])), 0.f), __ldg(&ss[c0 + 0]), __ldg(&tt[c0 + 0]));
    o.y = fmaf(fmaxf(fmaf(dv, a1, __ldg(&bb[c0 + 1])), 0.f), __ldg(&ss[c0 + 1]), __ldg(&tt[c0 + 1]));
    o.z = fmaf(fmaxf(fmaf(dv, a2, __ldg(&bb[c0 + 2])), 0.f), __ldg(&ss[c0 + 2]), __ldg(&tt[c0 + 2]));
    o.w = fmaf(fmaxf(fmaf(dv, a3, __ldg(&bb[c0 + 3])), 0.f), __ldg(&ss[c0 + 3]), __ldg(&tt[c0 + 3]));
    float4 ot = make_float4(0.f, 0.f, 0.f, 0.f);
    if (tl) {
        int ct = 128 + 4 * lane;
        ot.x = fmaf(fmaxf(fmaf(dv, t0, __ldg(&bb[ct + 0])), 0.f), __ldg(&ss[ct + 0]), __ldg(&tt[ct + 0]));
        ot.y = fmaf(fmaxf(fmaf(dv, t1, __ldg(&bb[ct + 1])), 0.f), __ldg(&ss[ct + 1]), __ldg(&tt[ct + 1]));
        ot.z = fmaf(fmaxf(fmaf(dv, t2, __ldg(&bb[ct + 2])), 0.f), __ldg(&ss[ct + 2]), __ldg(&tt[ct + 2]));
        ot.w = fmaf(fmaxf(fmaf(dv, t3, __ldg(&bb[ct + 3])), 0.f), __ldg(&ss[ct + 3]), __ldg(&tt[ct + 3]));
    }

    if (POOL == 0) {
        uint2* Cr = (uint2*)(g_X16 + (size_t)n * DPH);
        Cr[lane] = make_uint2(pack2h(o.x, o.y), pack2h(o.z, o.w));
        if (tl) Cr[32 + lane] = make_uint2(pack2h(ot.x, ot.y), pack2h(ot.z, ot.w));
        if (lane == 2)   // zero pads cols 136..143
            *(uint4*)(g_X16 + (size_t)n * DPH + 136) = make_uint4(0, 0, 0, 0);
    } else {
        int g = __ldg(&batch[n]);
        float* dst = g_P + (size_t)g * DP + c0;
        unsigned long long p0 = (unsigned long long)__cvta_generic_to_global(dst);
        asm volatile("red.global.add.v4.f32 [%0], {%1,%2,%3,%4};"
                     :: "l"(p0), "f"(o.x), "f"(o.y), "f"(o.z), "f"(o.w) : "memory");
        if (tl) {
            float* dt = g_P + (size_t)g * DP + 128 + 4 * lane;
            unsigned long long p1 = (unsigned long long)__cvta_generic_to_global(dt);
            asm volatile("red.global.add.v4.f32 [%0], {%1,%2,%3,%4};"
                         :: "l"(p1), "f"(ot.x), "f"(ot.y), "f"(ot.z), "f"(ot.w) : "memory");
        }
    }
}

// ------------------------------------------------------------------
__device__ __forceinline__ int lbound(const int* b, int n, int v) {
    int lo = 0, hi = n;
    while (lo < hi) { int m = (lo + hi) >> 1; if (b[m] < v) lo = m + 1; else hi = m; }
    return lo;
}

__global__ void cntg_kernel(const int* __restrict__ batch) {
    int g = blockIdx.x * blockDim.x + threadIdx.x;
    if (g < N_GRAPHS)
        g_cntg[g] = lbound(batch, N_NODES, g + 1) - lbound(batch, N_NODES, g);
}

__global__ void divide_kernel(float* __restrict__ out) {
    int idx = blockIdx.x * blockDim.x + threadIdx.x;
    if (idx >= N_GRAPHS * D) return;
    int g = idx / D;
    int c = idx - g * D;
    float cnt = (float)g_cntg[g];
    out[idx] = g_P[(size_t)g * DP + c] / fmaxf(cnt, 1.0f);
}

// ------------------------------------------------------------------
extern "C" void kernel_launch(void* const* d_in, const int* in_sizes, int n_in,
                              void* d_out, int out_size) {
    const float* x     = (const float*)d_in[0];
    const int*   ei    = (const int*)d_in[1];
    const int*   batch = (const int*)d_in[2];
    const float* W1  = (const float*)d_in[3];
    const float* b1  = (const float*)d_in[4];
    const float* W2  = (const float*)d_in[5];
    const float* b2  = (const float*)d_in[6];
    const float* g1  = (const float*)d_in[7];
    const float* be1 = (const float*)d_in[8];
    const float* rm1 = (const float*)d_in[9];
    const float* rv1 = (const float*)d_in[10];
    const float* g2  = (const float*)d_in[11];
    const float* be2 = (const float*)d_in[12];
    const float* rm2 = (const float*)d_in[13];
    const float* rv2 = (const float*)d_in[14];
    float* out = (float*)d_out;

    __half *pA, *pX, *pW2th;
    float *pP1, *pP2;
    cudaGetSymbolAddress((void**)&pA, g_A16);
    cudaGetSymbolAddress((void**)&pX, g_X16);
    cudaGetSymbolAddress((void**)&pP1, g_post1);
    cudaGetSymbolAddress((void**)&pP2, g_post2);
    cudaGetSymbolAddress((void**)&pW2th, g_W2th);

    // side stream + events, created once (no device allocation)
    static cudaStream_t s_side = nullptr;
    static cudaEvent_t ev_fork0 = nullptr, ev_cnt = nullptr, ev_prep = nullptr, ev_join = nullptr;
    if (!s_side) {
        cudaStreamCreateWithFlags(&s_side, cudaStreamNonBlocking);
        cudaEventCreateWithFlags(&ev_fork0, cudaEventDisableTiming);
        cudaEventCreateWithFlags(&ev_cnt, cudaEventDisableTiming);
        cudaEventCreateWithFlags(&ev_prep, cudaEventDisableTiming);
        cudaEventCreateWithFlags(&ev_join, cudaEventDisableTiming);
    }

    const int smem = WN * WKS * (int)sizeof(__half);            // 43.8 KB -> 4 blocks/SM
    cudaFuncSetAttribute((const void*)gemm_tc_kernel<true>,
                         cudaFuncAttributeMaxDynamicSharedMemorySize, smem);
    cudaFuncSetAttribute((const void*)gemm_tc_kernel<false>,
                         cudaFuncAttributeMaxDynamicSharedMemorySize, smem);

    const int TB = 256;
    const int gemm_blocks   = (N_NODES + 63) / 64;                // 782
    const int gather_blocks = (N_NODES * 32 + TB - 1) / TB;       // warp per node

    // ---- fork FIRST (capture-legal), then side does prep_x concurrently ----
    cudaEventRecord(ev_fork0, 0);
    cudaStreamWaitEvent(s_side, ev_fork0, 0);
    prep_x_kernel<<<(N_NODES * 36 + TB - 1) / TB, TB, 0, s_side>>>(x);
    cudaEventRecord(ev_prep, s_side);

    // ---- main: zero(2), count(3), gemm1(4th submission, ncu target) ----
    zero_fused_kernel<<<(N_GRAPHS * DP + TB - 1) / TB, TB>>>();
    count_deg_kernel<<<(N_EDGES + TB - 1) / TB, TB>>>(ei);
    cudaEventRecord(ev_cnt, 0);
    cudaStreamWaitEvent(0, ev_prep, 0);
    gemm_tc_kernel<true><<<gemm_blocks, TB, smem>>>(pX, W1, nullptr);

    // ---- side: CSR build + misc (needs count_deg), overlapped with gemm1 ----
    cudaStreamWaitEvent(s_side, ev_cnt, 0);
    scan1_kernel<<<SCAN_NB, SCAN_B, 0, s_side>>>();
    scan2_kernel<<<1, 32, 0, s_side>>>();
    scan3_kernel<<<SCAN_NB, SCAN_B, 0, s_side>>>();
    fill_csr_kernel<<<(N_EDGES + TB - 1) / TB, TB, 0, s_side>>>(ei);
    w_cvt_h_kernel<<<(WN * WKS + TB - 1) / TB, TB, 0, s_side>>>(W2, pW2th);
    prep_post_kernel<<<1, DP, 0, s_side>>>(b1, g1, be1, rm1, rv1, pP1);
    prep_post_kernel<<<1, DP, 0, s_side>>>(b2, g2, be2, rm2, rv2, pP2);
    cntg_kernel<<<(N_GRAPHS + TB - 1) / TB, TB, 0, s_side>>>(batch);
    cudaEventRecord(ev_join, s_side);

    // ---- join, then the serial tail ----
    cudaStreamWaitEvent(0, ev_join, 0);
    gather_post_kernel<0><<<gather_blocks, TB>>>(pA, pP1, batch);   // -> g_X16
    gemm_tc_kernel<false><<<gemm_blocks, TB, smem>>>(pX, nullptr, pW2th);
    gather_post_kernel<1><<<gather_blocks, TB>>>(pA, pP2, batch);   // -> g_P
    divide_kernel<<<(N_GRAPHS * D + TB - 1) / TB, TB>>>(out);
}

// round 17
// speedup vs baseline: 1.0303x; 1.0303x over previous
#include <cuda_runtime.h>
#include <cuda_fp16.h>
#include <cstdint>

#define N_NODES 50000
#define N_EDGES 1600000
#define N_GRAPHS 2048
#define D 133
#define DP 136           // fp32 padded row (floats)
#define DPH 144          // fp16 padded row (halves) = 288B (9 sectors)
#define WKS 152          // W smem k-stride in halves (bank-conflict-free)
#define EPSV 1e-5f
#define SCAN_B 1024
#define SCAN_NB ((N_NODES + SCAN_B - 1) / SCAN_B)   // 49

// -------- scratch (static device globals; no runtime allocation) --------
__device__ __align__(16) __half g_A16[(size_t)N_NODES * DPH];  // gemm out (messages)
__device__ __align__(16) __half g_X16[(size_t)N_NODES * DPH];  // gemm in
__device__ __align__(16) float  g_P[(size_t)N_GRAPHS * DP];    // pool accumulator
__device__ __align__(16) __half g_W2th[136 * WKS];             // W2 fp16, [n][k] transposed
__device__ int   g_cnt[N_NODES];
__device__ int   g_off[N_NODES + 1];
__device__ int   g_cursor[N_NODES];
__device__ int   g_csr[N_EDGES];
__device__ int   g_bsum[SCAN_NB];
__device__ int   g_cntg[N_GRAPHS];
__device__ float g_post1[3 * DP];    // bias | s | t   (zero-padded)
__device__ float g_post2[3 * DP];

// ------------------------------------------------------------------
__global__ void zero_fused_kernel() {
    int i = blockIdx.x * blockDim.x + threadIdx.x;
    if (i < N_GRAPHS * DP) g_P[i] = 0.0f;
    if (i < N_NODES)       g_cnt[i] = 0;
}

__global__ void count_deg_kernel(const int* __restrict__ ei) {
    int e = blockIdx.x * blockDim.x + threadIdx.x;
    if (e < N_EDGES) atomicAdd(&g_cnt[__ldg(&ei[N_EDGES + e])], 1);
}

__device__ __forceinline__ uint32_t pack2h(float x, float y) {
    __half2 h = __floats2half2_rn(x, y);
    return *(uint32_t*)&h;
}

// X (fp32 [N,133]) -> g_X16 (fp16 [N,144], pads 0). Independent of everything.
__global__ void prep_x_kernel(const float* __restrict__ X) {
    int idx = blockIdx.x * blockDim.x + threadIdx.x;
    if (idx >= N_NODES * 36) return;
    int row = idx / 36;
    int q   = idx - row * 36;
    int c   = 4 * q;
    const float* Xr = X + (size_t)row * D;
    float f0 = (c     < D) ? __ldg(Xr + c)     : 0.0f;
    float f1 = (c + 1 < D) ? __ldg(Xr + c + 1) : 0.0f;
    float f2 = (c + 2 < D) ? __ldg(Xr + c + 2) : 0.0f;
    float f3 = (c + 3 < D) ? __ldg(Xr + c + 3) : 0.0f;
    ((uint2*)(g_X16 + (size_t)row * DPH))[q] = make_uint2(pack2h(f0, f1), pack2h(f2, f3));
}

// ---- 3-kernel exclusive scan of g_cnt -> g_off ----
__global__ void scan1_kernel() {
    __shared__ int sh[SCAN_B];
    int t = threadIdx.x;
    int i = blockIdx.x * SCAN_B + t;
    int v = (i < N_NODES) ? g_cnt[i] : 0;
    sh[t] = v;
    __syncthreads();
#pragma unroll
    for (int d = 1; d < SCAN_B; d <<= 1) {
        int x = (t >= d) ? sh[t - d] : 0;
        __syncthreads();
        sh[t] += x;
        __syncthreads();
    }
    if (i < N_NODES) g_off[i] = sh[t] - v;
    if (t == SCAN_B - 1) g_bsum[blockIdx.x] = sh[t];
}

__global__ void scan2_kernel() {
    if (threadIdx.x == 0) {
        int acc = 0;
        for (int b = 0; b < SCAN_NB; b++) {
            int v = g_bsum[b];
            g_bsum[b] = acc;
            acc += v;
        }
    }
}

__global__ void scan3_kernel() {
    int i = blockIdx.x * blockDim.x + threadIdx.x;
    if (i < N_NODES) {
        int o = g_off[i] + g_bsum[i / SCAN_B];
        g_off[i] = o;
        g_cursor[i] = o;
    }
    if (i == 0) g_off[N_NODES] = N_EDGES;
}

__global__ void fill_csr_kernel(const int* __restrict__ ei) {
    int e = blockIdx.x * blockDim.x + threadIdx.x;
    if (e < N_EDGES) {
        int r = __ldg(&ei[e]);
        int c = __ldg(&ei[N_EDGES + e]);
        int pos = atomicAdd(&g_cursor[c], 1);
        g_csr[pos] = r;
    }
}

// ---- per-layer fused BN constants: bias | s | t, zero-padded to DP ----
__global__ void prep_post_kernel(const float* __restrict__ bias, const float* __restrict__ gam,
                                 const float* __restrict__ beta, const float* __restrict__ rm,
                                 const float* __restrict__ rv, float* __restrict__ dst) {
    int c = threadIdx.x;
    if (c >= DP) return;
    float bb = 0.0f, ss = 0.0f, tt = 0.0f;
    if (c < D) {
        bb = bias[c];
        float sc = gam[c] * rsqrtf(rv[c] + EPSV);
        ss = sc;
        tt = beta[c] - rm[c] * sc;
    }
    dst[c] = bb; dst[DP + c] = ss; dst[2 * DP + c] = tt;
}

// W2 -> fp16, transposed [n][k] with stride WKS, zero-padded
__global__ void w_cvt_h_kernel(const float* __restrict__ W, __half* __restrict__ Wt) {
    int i = blockIdx.x * blockDim.x + threadIdx.x;
    if (i >= 136 * WKS) return;
    int n = i / WKS, k = i - n * WKS;
    float v = (k < D && n < D) ? __ldg(&W[k * D + n]) : 0.0f;
    Wt[i] = __float2half(v);
}

__device__ __forceinline__ void mma_f16(float* d,
                                        uint32_t a0, uint32_t a1, uint32_t a2, uint32_t a3,
                                        uint32_t b0, uint32_t b1) {
    asm volatile("mma.sync.aligned.m16n8k16.row.col.f32.f16.f16.f32 "
                 "{%0,%1,%2,%3}, {%4,%5,%6,%7}, {%8,%9}, {%0,%1,%2,%3};"
                 : "+f"(d[0]), "+f"(d[1]), "+f"(d[2]), "+f"(d[3])
                 : "r"(a0), "r"(a1), "r"(a2), "r"(a3), "r"(b0), "r"(b1));
}

// Tensor-core GEMM (fp16 m16n8k16): g_A16[row] = fp16( rsqrt(cnt+1) * (Xh @ W) ).
// Round-13 structure: W smem [136][WKS]; n-split warp pairs (9/8 tiles).
template <bool CVT>
__global__ __launch_bounds__(256, 4)
void gemm_tc_kernel(const __half* __restrict__ Xh,
                    const float* __restrict__ Wf, const __half* __restrict__ Wth) {
    extern __shared__ __half wsh[];          // [136 n][WKS k] fp16

    int tid  = threadIdx.x;
    int w    = tid >> 5;
    int lane = tid & 31;

    if (CVT) {
        // layer 1: convert + transpose W (f32 [k][n] row-major -> wsh[n][k])
        for (int idx = tid; idx < 72 * 136; idx += 256) {
            int kp = idx / 136;
            int n  = idx - kp * 136;
            int k  = 2 * kp;
            float f0 = (k < D     && n < D) ? __ldg(&Wf[k * D + n])       : 0.0f;
            float f1 = (k + 1 < D && n < D) ? __ldg(&Wf[(k + 1) * D + n]) : 0.0f;
            *(uint32_t*)&wsh[n * WKS + k] = pack2h(f0, f1);
        }
        // zero the k in [144, WKS) pad region
        for (int idx = tid; idx < 136 * (WKS - 144) / 2; idx += 256) {
            int n = idx / ((WKS - 144) / 2);
            int r = idx - n * ((WKS - 144) / 2);
            *(uint32_t*)&wsh[n * WKS + 144 + 2 * r] = 0u;
        }
    } else {
        const uint4* src = (const uint4*)Wth;
        uint4* dst = (uint4*)wsh;
#pragma unroll 4
        for (int i = tid; i < (136 * WKS) / 8; i += 256) dst[i] = __ldg(&src[i]);
    }
    __syncthreads();

    const int r0 = lane >> 2;        // A row group / B n
    const int kc = lane & 3;         // A k quad / B k
    const int colhalf = w & 1;
    const int ntBase = colhalf * 9;
    const int ntCnt  = 9 - colhalf;  // 9 or 8 tiles

    int rowbase = blockIdx.x * 64 + (w >> 1) * 16;
    int row0 = rowbase + r0;
    int row1 = row0 + 8;
    bool v0 = row0 < N_NODES;
    bool v1 = row1 < N_NODES;
    const uint32_t* x0p = (const uint32_t*)(Xh + (size_t)(v0 ? row0 : 0) * DPH);
    const uint32_t* x1p = (const uint32_t*)(Xh + (size_t)(v1 ? row1 : 0) * DPH);

    const uint32_t* wb = (const uint32_t*)&wsh[(ntBase * 8 + r0) * WKS + 2 * kc];

    float acc[9][4];
#pragma unroll
    for (int j = 0; j < 9; j++)
#pragma unroll
        for (int q = 0; q < 4; q++) acc[j][q] = 0.0f;

    uint32_t a0 = __ldg(x0p + kc);
    uint32_t a1 = __ldg(x1p + kc);
    uint32_t a2 = __ldg(x0p + kc + 4);
    uint32_t a3 = __ldg(x1p + kc + 4);

#pragma unroll
    for (int ks = 0; ks < 9; ks++) {
        uint32_t na0 = 0, na1 = 0, na2 = 0, na3 = 0;
        if (ks < 8) {
            int wi = (ks + 1) * 8 + kc;
            na0 = __ldg(x0p + wi);
            na1 = __ldg(x1p + wi);
            na2 = __ldg(x0p + wi + 4);
            na3 = __ldg(x1p + wi + 4);
        }
#pragma unroll
        for (int j = 0; j < 9; j++) {
            if (j < ntCnt)
                mma_f16(acc[j], a0, a1, a2, a3,
                        wb[j * (4 * WKS) + ks * 8], wb[j * (4 * WKS) + ks * 8 + 4]);
        }
        a0 = na0; a1 = na1; a2 = na2; a3 = na3;
    }

    // epilogue: inline dinv = rsqrt(cnt+1); fp16 half2 stores (cols 133..135 via W pads)
    float dv0 = v0 ? rsqrtf((float)(__ldg(&g_cnt[row0]) + 1)) : 0.0f;
    float dv1 = v1 ? rsqrtf((float)(__ldg(&g_cnt[row1]) + 1)) : 0.0f;
    int cb = 2 * kc;
#pragma unroll
    for (int j = 0; j < 9; j++) {
        if (j < ntCnt) {
            int c = (ntBase + j) * 8 + cb;
            if (v0)
                *(__half2*)(g_A16 + (size_t)row0 * DPH + c) =
                    __floats2half2_rn(dv0 * acc[j][0], dv0 * acc[j][1]);
            if (v1)
                *(__half2*)(g_A16 + (size_t)row1 * DPH + c) =
                    __floats2half2_rn(dv1 * acc[j][2], dv1 * acc[j][3]);
        }
    }
}

// ------------------------------------------------------------------
// Warp-per-node CSR gather, full-warp lanes: lane l accumulates cols 4l..4l+3
// (uint2 = 2 half2); lanes 0-1 also handle tail cols 128..135. fp32 accum.
// POOL=0: write fp16 row (DPH, pads zeroed) to g_X16.  POOL=1: red.v4 into g_P.
template <int POOL>
__global__ __launch_bounds__(256)
void gather_post_kernel(const __half* __restrict__ A,
                        const float* __restrict__ post,
                        const int* __restrict__ batch) {
    int gw = (blockIdx.x * blockDim.x + threadIdx.x) >> 5;
    if (gw >= N_NODES) return;
    int lane = threadIdx.x & 31;
    int n = gw;

    int lo = __ldg(&g_off[n]);
    int hi = __ldg(&g_off[n + 1]);
    bool tl = lane < 2;

    float a0 = 0.f, a1 = 0.f, a2 = 0.f, a3 = 0.f;
    float t0 = 0.f, t1 = 0.f, t2 = 0.f, t3 = 0.f;

#define ACCUM(SJ) do {                                                        \
        const char* R = (const char*)(A + (size_t)(SJ) * DPH);                \
        uint2 m = __ldg((const uint2*)R + lane);                              \
        float2 f0 = __half22float2(*(const __half2*)&m.x);                    \
        float2 f1 = __half22float2(*(const __half2*)&m.y);                    \
        a0 += f0.x; a1 += f0.y; a2 += f1.x; a3 += f1.y;                       \
        if (tl) {                                                             \
            uint2 mt = __ldg((const uint2*)(R + 256) + lane);                 \
            float2 g0 = __half22float2(*(const __half2*)&mt.x);               \
            float2 g1 = __half22float2(*(const __half2*)&mt.y);               \
            t0 += g0.x; t1 += g0.y; t2 += g1.x; t3 += g1.y;                   \
        }                                                                     \
    } while (0)

    ACCUM(n);   // self-loop term

    int e = lo;
    for (; e + 32 <= hi; e += 32) {
        int src = __ldg(&g_csr[e + lane]);
#pragma unroll 4
        for (int j = 0; j < 32; j++) {
            int sj = __shfl_sync(0xffffffffu, src, j);
            ACCUM(sj);
        }
    }
    for (; e < hi; e++) {
        int sj = __ldg(&g_csr[e]);
        ACCUM(sj);
    }
#undef ACCUM

    float dv = rsqrtf((float)(__ldg(&g_cnt[n]) + 1));
    const float* bb = post;
    const float* ss = post + DP;
    const float* tt = post + 2 * DP;

    int c0 = 4 * lane;
    float4 o;
    o.x = fmaf(fmaxf(fmaf(dv, a0, __ldg(&bb[c0 + 0])), 0.f), __ldg(&ss[c0 + 0]), __ldg(&tt[c0 + 0]));
    o.y = fmaf(fmaxf(fmaf(dv, a1, __ldg(&bb[c0 + 1])), 0.f), __ldg(&ss[c0 + 1]), __ldg(&tt[c0 + 1]));
    o.z = fmaf(fmaxf(fmaf(dv, a2, __ldg(&bb[c0 + 2])), 0.f), __ldg(&ss[c0 + 2]), __ldg(&tt[c0 + 2]));
    o.w = fmaf(fmaxf(fmaf(dv, a3, __ldg(&bb[c0 + 3])), 0.f), __ldg(&ss[c0 + 3]), __ldg(&tt[c0 + 3]));
    float4 ot = make_float4(0.f, 0.f, 0.f, 0.f);
    if (tl) {
        int ct = 128 + 4 * lane;
        ot.x = fmaf(fmaxf(fmaf(dv, t0, __ldg(&bb[ct + 0])), 0.f), __ldg(&ss[ct + 0]), __ldg(&tt[ct + 0]));
        ot.y = fmaf(fmaxf(fmaf(dv, t1, __ldg(&bb[ct + 1])), 0.f), __ldg(&ss[ct + 1]), __ldg(&tt[ct + 1]));
        ot.z = fmaf(fmaxf(fmaf(dv, t2, __ldg(&bb[ct + 2])), 0.f), __ldg(&ss[ct + 2]), __ldg(&tt[ct + 2]));
        ot.w = fmaf(fmaxf(fmaf(dv, t3, __ldg(&bb[ct + 3])), 0.f), __ldg(&ss[ct + 3]), __ldg(&tt[ct + 3]));
    }

    if (POOL == 0) {
        uint2* Cr = (uint2*)(g_X16 + (size_t)n * DPH);
        Cr[lane] = make_uint2(pack2h(o.x, o.y), pack2h(o.z, o.w));
        if (tl) Cr[32 + lane] = make_uint2(pack2h(ot.x, ot.y), pack2h(ot.z, ot.w));
        if (lane == 2)   // zero pads cols 136..143
            *(uint4*)(g_X16 + (size_t)n * DPH + 136) = make_uint4(0, 0, 0, 0);
    } else {
        int g = __ldg(&batch[n]);
        float* dst = g_P + (size_t)g * DP + c0;
        unsigned long long p0 = (unsigned long long)__cvta_generic_to_global(dst);
        asm volatile("red.global.add.v4.f32 [%0], {%1,%2,%3,%4};"
                     :: "l"(p0), "f"(o.x), "f"(o.y), "f"(o.z), "f"(o.w) : "memory");
        if (tl) {
            float* dt = g_P + (size_t)g * DP + 128 + 4 * lane;
            unsigned long long p1 = (unsigned long long)__cvta_generic_to_global(dt);
            asm volatile("red.global.add.v4.f32 [%0], {%1,%2,%3,%4};"
                         :: "l"(p1), "f"(ot.x), "f"(ot.y), "f"(ot.z), "f"(ot.w) : "memory");
        }
    }
}

// ------------------------------------------------------------------
__device__ __forceinline__ int lbound(const int* b, int n, int v) {
    int lo = 0, hi = n;
    while (lo < hi) { int m = (lo + hi) >> 1; if (b[m] < v) lo = m + 1; else hi = m; }
    return lo;
}

__global__ void cntg_kernel(const int* __restrict__ batch) {
    int g = blockIdx.x * blockDim.x + threadIdx.x;
    if (g < N_GRAPHS)
        g_cntg[g] = lbound(batch, N_NODES, g + 1) - lbound(batch, N_NODES, g);
}

__global__ void divide_kernel(float* __restrict__ out) {
    int idx = blockIdx.x * blockDim.x + threadIdx.x;
    if (idx >= N_GRAPHS * D) return;
    int g = idx / D;
    int c = idx - g * D;
    float cnt = (float)g_cntg[g];
    out[idx] = g_P[(size_t)g * DP + c] / fmaxf(cnt, 1.0f);
}

// ------------------------------------------------------------------
extern "C" void kernel_launch(void* const* d_in, const int* in_sizes, int n_in,
                              void* d_out, int out_size) {
    const float* x     = (const float*)d_in[0];
    const int*   ei    = (const int*)d_in[1];
    const int*   batch = (const int*)d_in[2];
    const float* W1  = (const float*)d_in[3];
    const float* b1  = (const float*)d_in[4];
    const float* W2  = (const float*)d_in[5];
    const float* b2  = (const float*)d_in[6];
    const float* g1  = (const float*)d_in[7];
    const float* be1 = (const float*)d_in[8];
    const float* rm1 = (const float*)d_in[9];
    const float* rv1 = (const float*)d_in[10];
    const float* g2  = (const float*)d_in[11];
    const float* be2 = (const float*)d_in[12];
    const float* rm2 = (const float*)d_in[13];
    const float* rv2 = (const float*)d_in[14];
    float* out = (float*)d_out;

    __half *pA, *pX, *pW2th;
    float *pP1, *pP2;
    cudaGetSymbolAddress((void**)&pA, g_A16);
    cudaGetSymbolAddress((void**)&pX, g_X16);
    cudaGetSymbolAddress((void**)&pP1, g_post1);
    cudaGetSymbolAddress((void**)&pP2, g_post2);
    cudaGetSymbolAddress((void**)&pW2th, g_W2th);

    // side stream + events, created once (no device allocation)
    static cudaStream_t s_side = nullptr;
    static cudaEvent_t ev_fork0 = nullptr, ev_cnt = nullptr, ev_prep = nullptr, ev_join = nullptr;
    if (!s_side) {
        cudaStreamCreateWithFlags(&s_side, cudaStreamNonBlocking);
        cudaEventCreateWithFlags(&ev_fork0, cudaEventDisableTiming);
        cudaEventCreateWithFlags(&ev_cnt, cudaEventDisableTiming);
        cudaEventCreateWithFlags(&ev_prep, cudaEventDisableTiming);
        cudaEventCreateWithFlags(&ev_join, cudaEventDisableTiming);
    }

    const int smem = 136 * WKS * (int)sizeof(__half);           // 41.3 KB
    cudaFuncSetAttribute((const void*)gemm_tc_kernel<true>,
                         cudaFuncAttributeMaxDynamicSharedMemorySize, smem);
    cudaFuncSetAttribute((const void*)gemm_tc_kernel<false>,
                         cudaFuncAttributeMaxDynamicSharedMemorySize, smem);

    const int TB = 256;
    const int gemm_blocks   = (N_NODES + 63) / 64;                // 782
    const int gather_blocks = (N_NODES * 32 + TB - 1) / TB;       // warp per node

    // ---- fork FIRST (capture-legal), then side does prep_x concurrently ----
    cudaEventRecord(ev_fork0, 0);
    cudaStreamWaitEvent(s_side, ev_fork0, 0);
    prep_x_kernel<<<(N_NODES * 36 + TB - 1) / TB, TB, 0, s_side>>>(x);
    cudaEventRecord(ev_prep, s_side);

    // ---- main: zero(2), count(3), gemm1(4th submission, ncu target) ----
    zero_fused_kernel<<<(N_GRAPHS * DP + TB - 1) / TB, TB>>>();
    count_deg_kernel<<<(N_EDGES + TB - 1) / TB, TB>>>(ei);
    cudaEventRecord(ev_cnt, 0);
    cudaStreamWaitEvent(0, ev_prep, 0);
    gemm_tc_kernel<true><<<gemm_blocks, TB, smem>>>(pX, W1, nullptr);

    // ---- side: CSR build + misc (needs count_deg), overlapped with gemm1 ----
    cudaStreamWaitEvent(s_side, ev_cnt, 0);
    scan1_kernel<<<SCAN_NB, SCAN_B, 0, s_side>>>();
    scan2_kernel<<<1, 32, 0, s_side>>>();
    scan3_kernel<<<SCAN_NB, SCAN_B, 0, s_side>>>();
    fill_csr_kernel<<<(N_EDGES + TB - 1) / TB, TB, 0, s_side>>>(ei);
    w_cvt_h_kernel<<<(136 * WKS + TB - 1) / TB, TB, 0, s_side>>>(W2, pW2th);
    prep_post_kernel<<<1, DP, 0, s_side>>>(b1, g1, be1, rm1, rv1, pP1);
    prep_post_kernel<<<1, DP, 0, s_side>>>(b2, g2, be2, rm2, rv2, pP2);
    cntg_kernel<<<(N_GRAPHS + TB - 1) / TB, TB, 0, s_side>>>(batch);
    cudaEventRecord(ev_join, s_side);

    // ---- join, then the serial tail ----
    cudaStreamWaitEvent(0, ev_join, 0);
    gather_post_kernel<0><<<gather_blocks, TB>>>(pA, pP1, batch);   // -> g_X16
    gemm_tc_kernel<false><<<gemm_blocks, TB, smem>>>(pX, nullptr, pW2th);
    gather_post_kernel<1><<<gather_blocks, TB>>>(pA, pP2, batch);   // -> g_P
    divide_kernel<<<(N_GRAPHS * D + TB - 1) / TB, TB>>>(out);
}